// round 16
// baseline (speedup 1.0000x reference)
#include <cuda_runtime.h>
#include <cuda_bf16.h>
#include <math.h>
#include <stdint.h>

// Problem constants
#define BSZ   512
#define TT    64
#define TTOT  65
#define FEAT  512
#define HID   1000
#define GAPS  16
#define EPSV  1e-5f
#define SCAN_GRID 128
#define PDEC_GRID 128
#define NOROW (1 << 30)

// ---------------- scratch (device globals; allocation-free) ----------------
__device__ float g_prex[TT * BSZ * FEAT];
__device__ float g_hs  [TT * BSZ * FEAT];
__device__ float g_z1  [TT * BSZ * HID];
__device__ float g_z2  [TT * BSZ * HID];
__device__ float g_y   [TT * BSZ * FEAT];
__device__ float g_xall[GAPS * BSZ * FEAT];
__device__ float g_hA  [BSZ * FEAT];
__device__ float g_hB  [BSZ * FEAT];
__device__ float g_z1d [BSZ * HID];
__device__ float g_z2d [BSZ * HID];
// tf32-pre-rounded copies
__device__ float g_xr  [TTOT * BSZ * FEAT];
__device__ float g_wih [FEAT * FEAT];
__device__ float g_whh [FEAT * FEAT];
__device__ float g_w1  [HID * FEAT];
__device__ float g_w2  [HID * HID];
__device__ float g_w3  [FEAT * HID];
__device__ double g_loss[2];
__device__ int    g_bar;    // scan barrier
__device__ int    g_bar2;   // decode barrier

// ---------------- tf32 helpers ----------------
__device__ __forceinline__ uint32_t f2tf(float f) {
    uint32_t u;
    asm("cvt.rna.tf32.f32 %0, %1;" : "=r"(u) : "f"(f));
    return u;
}
__device__ __forceinline__ float rndtf(float f) { return __uint_as_float(f2tf(f)); }

__device__ __forceinline__ void mma_tf32(float* c, const uint32_t* a,
                                         const uint32_t* b) {
    asm volatile(
        "mma.sync.aligned.m16n8k8.row.col.f32.tf32.tf32.f32 "
        "{%0,%1,%2,%3}, {%4,%5,%6,%7}, {%8,%9}, {%0,%1,%2,%3};"
        : "+f"(c[0]), "+f"(c[1]), "+f"(c[2]), "+f"(c[3])
        : "r"(a[0]), "r"(a[1]), "r"(a[2]), "r"(a[3]), "r"(b[0]), "r"(b[1]));
}
__device__ __forceinline__ void cpa16(uint32_t dst, const float* src, int sz) {
    asm volatile("cp.async.cg.shared.global [%0], [%1], 16, %2;"
                 :: "r"(dst), "l"(src), "r"(sz));
}

// ============ tf32 tensor GEMM, cp.async 3-stage, 128x128 tile ==============
// MODE 0: acc+bias  MODE 1: tanh(acc+bias+bias2)  MODE 2: BN  MODE 3: BN+loss1
template<int MODE, int DUAL>
__global__ void __launch_bounds__(256, 2) tgemm_k(
    const float* __restrict__ A,  const float* __restrict__ W,  int K,
    const float* __restrict__ A2, const float* __restrict__ W2,
    const float* __restrict__ bias, const float* __restrict__ bias2,
    const float* __restrict__ gam, const float* __restrict__ rm,
    const float* __restrict__ rv,  const float* __restrict__ bet,
    float* __restrict__ C, int M, int N,
    int rowDiv, int rowS1, int rowS2)
{
    extern __shared__ uint32_t smw[];

    const int tid  = threadIdx.x;
    const int lane = tid & 31;
    const int warp = tid >> 5;
    const int gid  = lane >> 2;
    const int tg   = lane & 3;
    const int wm   = warp & 3;
    const int wn   = warp >> 2;
    const int bm0  = blockIdx.y * 128;
    const int bn0  = blockIdx.x * 128;
    const int swz  = gid << 2;

    const int KC1 = (K + 31) >> 5;
    const int KCT = DUAL ? 2 * KC1 : KC1;

    long aoff0[4], boff[4];
    uint32_t dA[4];
    bool bvalid[4];
    const uint32_t smem0 = (uint32_t)__cvta_generic_to_shared(smw);
#pragma unroll
    for (int i = 0; i < 4; i++) {
        int idx = tid + i * 256;
        int r   = idx >> 3;
        int kq  = (idx & 7) * 4;
        int gm  = bm0 + r;
        aoff0[i] = (long)(gm / rowDiv) * rowS1 + (long)(gm % rowDiv) * rowS2 + kq;
        int gn = bn0 + r;
        bvalid[i] = gn < N;
        boff[i] = (long)(bvalid[i] ? gn : 0) * K + kq;
        dA[i] = smem0 + (uint32_t)(r * 32 + (kq ^ ((r & 7) << 2))) * 4;
    }

    auto issue = [&](int t) {
        uint32_t sb = (uint32_t)(t % 3) * 32768u;
        const float* Ap; const float* Wp; int k0; bool p0;
        if (!DUAL || t < KC1) { Ap = A;  Wp = W;  k0 = t << 5;         p0 = true; }
        else                  { Ap = A2; Wp = W2; k0 = (t - KC1) << 5; p0 = false; }
#pragma unroll
        for (int i = 0; i < 4; i++) {
            int idx = tid + i * 256;
            int r   = idx >> 3;
            int kq  = (idx & 7) * 4;
            int sz  = (k0 + kq + 3 < K) ? 16 : 0;
            long ao = p0 ? aoff0[i] : ((long)(bm0 + r) * K + kq);
            cpa16(dA[i] + sb,          Ap + ao + k0,      sz);
            cpa16(dA[i] + sb + 16384u, Wp + boff[i] + k0, bvalid[i] ? sz : 0);
        }
        asm volatile("cp.async.commit_group;");
    };

    float c[2][8][4];
#pragma unroll
    for (int i = 0; i < 2; i++)
#pragma unroll
        for (int j = 0; j < 8; j++)
#pragma unroll
            for (int r = 0; r < 4; r++) c[i][j][r] = 0.f;

    issue(0);
    issue(1);

    for (int t = 0; t < KCT; t++) {
        if (t == KCT - 1) asm volatile("cp.async.wait_group 0;");
        else              asm volatile("cp.async.wait_group 1;");
        __syncthreads();
        if (t + 2 < KCT) issue(t + 2);   // buffer (t+2)%3 consumed at t-1
        const uint32_t* Asb = smw + (t % 3) * 8192;
        const uint32_t* Bsb = Asb + 4096;
#pragma unroll
        for (int kt = 0; kt < 4; kt++) {
            const int klo = ((kt << 3) + tg) ^ swz;
            const int khi = klo ^ 4;
            uint32_t bfr[8][2];
#pragma unroll
            for (int nt = 0; nt < 8; nt++) {
                int nrow = (wn * 64 + nt * 8 + gid) << 5;
                bfr[nt][0] = Bsb[nrow + klo];
                bfr[nt][1] = Bsb[nrow + khi];
            }
            uint32_t afr[2][4];
#pragma unroll
            for (int mt = 0; mt < 2; mt++) {
                int mrow = (wm * 32 + mt * 16 + gid) << 5;
                afr[mt][0] = Asb[mrow + klo];
                afr[mt][1] = Asb[mrow + 256 + klo];
                afr[mt][2] = Asb[mrow + khi];
                afr[mt][3] = Asb[mrow + 256 + khi];
            }
#pragma unroll
            for (int mt = 0; mt < 2; mt++)
#pragma unroll
                for (int nt = 0; nt < 8; nt++)
                    mma_tf32(c[mt][nt], afr[mt], bfr[nt]);
        }
        __syncthreads();   // writers of (t+1)%3 must not race readers of t%3
    }

    float lacc = 0.f;
#pragma unroll
    for (int nt = 0; nt < 8; nt++) {
#pragma unroll
        for (int e = 0; e < 2; e++) {
            int col = bn0 + wn * 64 + nt * 8 + tg * 2 + e;
            if (col >= N) continue;
            float pb  = bias[col];
            float pb2 = (MODE == 1) ? bias2[col] : 0.f;
            float prm = 0.f, psc = 0.f, pbe = 0.f;
            if (MODE >= 2) {
                prm = rm[col];
                psc = gam[col] * rsqrtf(rv[col] + EPSV);
                pbe = bet[col];
            }
#pragma unroll
            for (int mt = 0; mt < 2; mt++)
#pragma unroll
                for (int h = 0; h < 2; h++) {
                    int row = bm0 + wm * 32 + mt * 16 + gid + h * 8;
                    float v = c[mt][nt][h * 2 + e] + pb;
                    if (MODE == 1) v = tanhf(v + pb2);
                    if (MODE >= 2) v = (v - prm) * psc + pbe;
                    float w = rndtf(v);
                    C[(long)row * N + col] = w;
                    if (MODE == 3 && row < (TT - 1) * BSZ) {
                        int tt2 = row >> 9, b = row & (BSZ - 1);
                        float d = w - A2[((long)b * TTOT + tt2 + 1) * FEAT + col];
                        lacc = fmaf(d, d, lacc);
                    }
                }
        }
    }
    if (MODE == 3) {
        __syncthreads();
        double* rd = (double*)smw;
        rd[tid] = (double)lacc;
        __syncthreads();
        for (int o = 128; o > 0; o >>= 1) {
            if (tid < o) rd[tid] += rd[tid + o];
            __syncthreads();
        }
        if (tid == 0) atomicAdd(&g_loss[0], rd[0]);
    }
}

// ============ 64x64x32 tile GEMM body (device fn, used by pdec_k) ===========
template<int MODE, int DUAL>
__device__ __forceinline__ void gemm64_tile(
    uint32_t* smw,
    const float* __restrict__ A,  const float* __restrict__ W,  int K,
    const float* __restrict__ A2, const float* __restrict__ W2,
    const float* __restrict__ bias, const float* __restrict__ bias2,
    const float* __restrict__ gam, const float* __restrict__ rm,
    const float* __restrict__ rv,  const float* __restrict__ bet,
    float* __restrict__ C, int N, int bm0, int bn0)
{
    const int tid  = threadIdx.x;
    const int lane = tid & 31;
    const int warp = tid >> 5;
    const int gid  = lane >> 2;
    const int tg   = lane & 3;
    const int wm   = warp & 3;
    const int wn   = warp >> 2;
    const int swz  = gid << 2;

    const int KC1 = (K + 31) >> 5;
    const int KCT = DUAL ? 2 * KC1 : KC1;

    long boff[2];
    uint32_t dA[2];
    int arow[2], akq[2];
    bool bvalid[2];
    const uint32_t smem0 = (uint32_t)__cvta_generic_to_shared(smw);
#pragma unroll
    for (int i = 0; i < 2; i++) {
        int idx = tid + i * 256;
        arow[i] = idx >> 3;
        akq[i]  = (idx & 7) * 4;
        int gn = bn0 + arow[i];
        bvalid[i] = gn < N;
        boff[i] = (long)(bvalid[i] ? gn : 0) * K + akq[i];
        dA[i] = smem0 +
                (uint32_t)(arow[i] * 32 + (akq[i] ^ ((arow[i] & 7) << 2))) * 4;
    }

    auto issue = [&](int t) {
        uint32_t sb = (uint32_t)(t % 3) * 16384u;
        const float* Ap; const float* Wp; int k0;
        if (!DUAL || t < KC1) { Ap = A;  Wp = W;  k0 = t << 5; }
        else                  { Ap = A2; Wp = W2; k0 = (t - KC1) << 5; }
#pragma unroll
        for (int i = 0; i < 2; i++) {
            int sz = (k0 + akq[i] + 3 < K) ? 16 : 0;
            cpa16(dA[i] + sb,
                  Ap + (long)(bm0 + arow[i]) * K + akq[i] + k0, sz);
            cpa16(dA[i] + sb + 8192u, Wp + boff[i] + k0, bvalid[i] ? sz : 0);
        }
        asm volatile("cp.async.commit_group;");
    };

    float c[4][4];
#pragma unroll
    for (int j = 0; j < 4; j++)
#pragma unroll
        for (int r = 0; r < 4; r++) c[j][r] = 0.f;

    issue(0);
    issue(1);

    for (int t = 0; t < KCT; t++) {
        if (t == KCT - 1) asm volatile("cp.async.wait_group 0;");
        else              asm volatile("cp.async.wait_group 1;");
        __syncthreads();
        if (t + 2 < KCT) issue(t + 2);
        const uint32_t* Asb = smw + (t % 3) * 4096;
        const uint32_t* Bsb = Asb + 2048;
#pragma unroll
        for (int kt = 0; kt < 4; kt++) {
            const int klo = ((kt << 3) + tg) ^ swz;
            const int khi = klo ^ 4;
            uint32_t afr[4];
            {
                int mrow = (wm * 16 + gid) << 5;
                afr[0] = Asb[mrow + klo];
                afr[1] = Asb[mrow + 256 + klo];
                afr[2] = Asb[mrow + khi];
                afr[3] = Asb[mrow + 256 + khi];
            }
#pragma unroll
            for (int nt = 0; nt < 4; nt++) {
                int nrow = (wn * 32 + nt * 8 + gid) << 5;
                uint32_t bfr[2];
                bfr[0] = Bsb[nrow + klo];
                bfr[1] = Bsb[nrow + khi];
                mma_tf32(c[nt], afr, bfr);
            }
        }
        __syncthreads();
    }

#pragma unroll
    for (int nt = 0; nt < 4; nt++) {
#pragma unroll
        for (int e = 0; e < 2; e++) {
            int col = bn0 + wn * 32 + nt * 8 + tg * 2 + e;
            if (col >= N) continue;
            float pb  = bias[col];
            float pb2 = (MODE == 1) ? bias2[col] : 0.f;
            float prm = 0.f, psc = 0.f, pbe = 0.f;
            if (MODE == 2) {
                prm = rm[col];
                psc = gam[col] * rsqrtf(rv[col] + EPSV);
                pbe = bet[col];
            }
#pragma unroll
            for (int h = 0; h < 2; h++) {
                int row = bm0 + wm * 16 + gid + h * 8;
                float v = c[nt][h * 2 + e] + pb;
                if (MODE == 1) v = tanhf(v + pb2);
                if (MODE == 2) v = (v - prm) * psc + pbe;
                C[(long)row * N + col] = rndtf(v);
            }
        }
    }
}

// ============== persistent fused decode: all 16 iterations ==================
__global__ void __launch_bounds__(256) pdec_k(
    const float* __restrict__ hs, const float* __restrict__ y,
    const float* __restrict__ wih, const float* __restrict__ whh,
    const float* __restrict__ b_ih, const float* __restrict__ b_hh,
    const float* __restrict__ w1, const float* __restrict__ b1,
    const float* __restrict__ g1, const float* __restrict__ rm1,
    const float* __restrict__ rv1, const float* __restrict__ be1,
    const float* __restrict__ w2, const float* __restrict__ b2,
    const float* __restrict__ g2, const float* __restrict__ rm2,
    const float* __restrict__ rv2, const float* __restrict__ be2,
    const float* __restrict__ w3, const float* __restrict__ b3,
    const float* __restrict__ g3, const float* __restrict__ rm3,
    const float* __restrict__ rv3, const float* __restrict__ be3,
    float* __restrict__ hA, float* __restrict__ hB,
    float* __restrict__ z1d, float* __restrict__ z2d,
    float* __restrict__ xall)
{
    extern __shared__ uint32_t smw[];
    const int bid = blockIdx.x;
    const int BF  = BSZ * FEAT;
    int tgt = 0;

    auto gbar = [&]() {
        tgt += PDEC_GRID;
        __syncthreads();
        if (threadIdx.x == 0) {
            __threadfence();
            atomicAdd(&g_bar2, 1);
            while (*(volatile int*)&g_bar2 < tgt) __nanosleep(64);
            __threadfence();
        }
        __syncthreads();
    };

    const float* hprev = hs + (size_t)(TT - 1) * BF;
    const float* xprev = y  + (size_t)(TT - 1) * BF;
    for (int g = 0; g < GAPS; g++) {
        float* hcur = (g & 1) ? hB : hA;
        float* xcur = xall + (size_t)g * BF;
        // S0: cell (dual) — 64 tiles
        if (bid < 64)
            gemm64_tile<1, 1>(smw, xprev, wih, FEAT, hprev, whh,
                              b_ih, b_hh, nullptr, nullptr, nullptr, nullptr,
                              hcur, FEAT, (bid >> 3) * 64, (bid & 7) * 64);
        gbar();
        // S1: z1d = BN1(hcur@w1) — 128 tiles (8 x 16)
        gemm64_tile<2, 0>(smw, hcur, w1, FEAT, nullptr, nullptr,
                          b1, nullptr, g1, rm1, rv1, be1,
                          z1d, HID, (bid >> 4) * 64, (bid & 15) * 64);
        gbar();
        // S2: z2d = BN2(z1d@w2) — 128 tiles
        gemm64_tile<2, 0>(smw, z1d, w2, HID, nullptr, nullptr,
                          b2, nullptr, g2, rm2, rv2, be2,
                          z2d, HID, (bid >> 4) * 64, (bid & 15) * 64);
        gbar();
        // S3: xcur = BN3(z2d@w3) — 64 tiles
        if (bid < 64)
            gemm64_tile<2, 0>(smw, z2d, w3, HID, nullptr, nullptr,
                              b3, nullptr, g3, rm3, rv3, be3,
                              xcur, FEAT, (bid >> 3) * 64, (bid & 7) * 64);
        gbar();
        hprev = hcur;
        xprev = xcur;
    }
}

// ============== persistent TENSOR-CORE RNN scan =============================
__global__ void __launch_bounds__(256) scan_k(const float* __restrict__ prex,
                                              const float* __restrict__ whh,
                                              const float* __restrict__ b_hh,
                                              float* __restrict__ hs)
{
    extern __shared__ uint32_t sm[];
    uint32_t* Wt  = sm;
    uint32_t* Ad  = sm + 16384;

    const int tid  = threadIdx.x;
    const int lane = tid & 31;
    const int warp = tid >> 5;
    const int gid  = lane >> 2;
    const int tg   = lane & 3;
    const int wm   = warp & 3;
    const int wn   = warp >> 2;
    const int nb   = blockIdx.x & 15;
    const int mb   = blockIdx.x >> 4;
    const int n0   = nb * 32;
    const int m0   = mb * 64;
    const int swz  = gid << 2;

    for (int idx = tid; idx < 32 * 512; idx += 256) {
        int n = idx >> 9, k = idx & 511;
        Wt[n * 512 + (k & ~31) + ((k & 31) ^ ((n & 7) << 2))] =
            __float_as_uint(whh[(n0 + n) * FEAT + k]);
    }

    const uint32_t smemA = (uint32_t)__cvta_generic_to_shared(Ad);
    uint32_t dA[2];
    int arow[2], akq[2];
#pragma unroll
    for (int i = 0; i < 2; i++) {
        int idx = tid + i * 256;
        arow[i] = idx >> 3;
        akq[i]  = (idx & 7) * 4;
        dA[i] = smemA + (uint32_t)(arow[i] * 32 + (akq[i] ^ ((arow[i] & 7) << 2))) * 4;
    }
    __syncthreads();

    int tgt = 0;
    for (int s = 0; s < TT; s++) {
        float c[2][4];
#pragma unroll
        for (int j = 0; j < 2; j++)
#pragma unroll
            for (int r = 0; r < 4; r++) c[j][r] = 0.f;

        if (s > 0) {
            const float* hp = hs + (size_t)(s - 1) * BSZ * FEAT;
            auto issueA = [&](int ch) {
                uint32_t sb = (uint32_t)(ch & 1) * 8192u;
#pragma unroll
                for (int i = 0; i < 2; i++)
                    cpa16(dA[i] + sb,
                          hp + (m0 + arow[i]) * FEAT + ch * 32 + akq[i], 16);
                asm volatile("cp.async.commit_group;");
            };
            issueA(0);
            issueA(1);
            for (int ch = 0; ch < 16; ch++) {
                if (ch == 15) asm volatile("cp.async.wait_group 0;");
                else          asm volatile("cp.async.wait_group 1;");
                __syncthreads();
                const uint32_t* Asb = Ad + (ch & 1) * 2048;
                const uint32_t* Wc  = Wt + ch * 32;
#pragma unroll
                for (int kt = 0; kt < 4; kt++) {
                    const int klo = ((kt << 3) + tg) ^ swz;
                    const int khi = klo ^ 4;
                    uint32_t afr[4];
                    int mrow = (wm * 16 + gid) << 5;
                    afr[0] = Asb[mrow + klo];
                    afr[1] = Asb[mrow + 256 + klo];
                    afr[2] = Asb[mrow + khi];
                    afr[3] = Asb[mrow + 256 + khi];
#pragma unroll
                    for (int nt = 0; nt < 2; nt++) {
                        int nrow = (wn * 16 + nt * 8 + gid) << 9;
                        uint32_t bfr[2];
                        bfr[0] = Wc[nrow + klo];
                        bfr[1] = Wc[nrow + khi];
                        mma_tf32(c[nt], afr, bfr);
                    }
                }
                __syncthreads();
                if (ch + 2 < 16) issueA(ch + 2);
            }
        }
        const float* px = prex + (size_t)s * BSZ * FEAT;
        float*       ho = hs   + (size_t)s * BSZ * FEAT;
#pragma unroll
        for (int nt = 0; nt < 2; nt++) {
            int col = n0 + wn * 16 + nt * 8 + tg * 2;
            float b0 = b_hh[col], b1 = b_hh[col + 1];
#pragma unroll
            for (int h = 0; h < 2; h++) {
                int row = m0 + wm * 16 + gid + h * 8;
                const float2 p = *reinterpret_cast<const float2*>(
                    px + (size_t)row * FEAT + col);
                float2 o;
                o.x = rndtf(tanhf(c[nt][h * 2 + 0] + p.x + b0));
                o.y = rndtf(tanhf(c[nt][h * 2 + 1] + p.y + b1));
                *reinterpret_cast<float2*>(ho + (size_t)row * FEAT + col) = o;
            }
        }
        tgt += SCAN_GRID;
        __syncthreads();
        if (tid == 0) {
            __threadfence();
            atomicAdd(&g_bar, 1);
            while (*(volatile int*)&g_bar < tgt) __nanosleep(64);
            __threadfence();
        }
        __syncthreads();
    }
}

// ----------------------------- misc kernels --------------------------------
__global__ void round_all_k(const float* __restrict__ x,
                            const float* __restrict__ wih_s,
                            const float* __restrict__ whh_s,
                            const float* __restrict__ w1_s,
                            const float* __restrict__ w2_s,
                            const float* __restrict__ w3_s)
{
    if (blockIdx.x == 0 && threadIdx.x == 0) {
        g_loss[0] = 0.0; g_loss[1] = 0.0; g_bar = 0; g_bar2 = 0;
    }
    const int N0 = TTOT * BSZ * FEAT;
    const int N1 = N0 + FEAT * FEAT;
    const int N2 = N1 + FEAT * FEAT;
    const int N3 = N2 + HID * FEAT;
    const int N4 = N3 + HID * HID;
    const int N5 = N4 + FEAT * HID;
    for (int i = blockIdx.x * blockDim.x + threadIdx.x; i < N5;
         i += gridDim.x * blockDim.x) {
        if      (i < N0) g_xr [i]      = rndtf(x[i]);
        else if (i < N1) g_wih[i - N0] = rndtf(wih_s[i - N0]);
        else if (i < N2) g_whh[i - N1] = rndtf(whh_s[i - N1]);
        else if (i < N3) g_w1 [i - N2] = rndtf(w1_s[i - N2]);
        else if (i < N4) g_w2 [i - N3] = rndtf(w2_s[i - N3]);
        else             g_w3 [i - N4] = rndtf(w3_s[i - N4]);
    }
}

__global__ void gather_k(const float* __restrict__ xall, const int* __restrict__ tt,
                         const float* __restrict__ x, float* __restrict__ out)
{
    __shared__ double sm[256];
    int idx = blockIdx.x * blockDim.x + threadIdx.x;
    int b = idx >> 9, f = idx & (FEAT - 1);
    int g = tt[b] - 1;
    float v = xall[(g * BSZ + b) * FEAT + f];
    out[idx] = v;
    float d = v - x[(b * TTOT + TTOT - 1) * FEAT + f];
    sm[threadIdx.x] = (double)d * (double)d;
    __syncthreads();
    for (int o = 128; o > 0; o >>= 1) {
        if (threadIdx.x < o) sm[threadIdx.x] += sm[threadIdx.x + o];
        __syncthreads();
    }
    if (threadIdx.x == 0) atomicAdd(&g_loss[1], sm[0]);
}

__global__ void fin_k(float* __restrict__ out)
{
    const double n1 = (double)(TT - 1) * BSZ * FEAT;
    const double n2 = (double)BSZ * FEAT;
    out[BSZ * FEAT] = (float)(g_loss[0] / (n1 * n1) + g_loss[1] / (n2 * n2));
}

// --------------------------- host orchestration ----------------------------
#define TG_SMEM 98304
#define PD_SMEM 49152
#define SC_SMEM 81920

template<int MODE>
static void runtg(const float* A, const float* W, int K, const float* bias,
                  const float* gam, const float* rm,
                  const float* rv, const float* bet, float* C,
                  int M, int N, int rowDiv, int rowS1, int rowS2,
                  const float* xref = nullptr)
{
    dim3 grid((N + 127) / 128, M / 128);
    tgemm_k<MODE, 0><<<grid, 256, TG_SMEM>>>(A, W, K, xref, nullptr,
                                             bias, nullptr, gam, rm, rv, bet,
                                             C, M, N, rowDiv, rowS1, rowS2);
}

extern "C" void kernel_launch(void* const* d_in, const int* in_sizes, int n_in,
                              void* d_out, int out_size)
{
    const float* x    = (const float*)d_in[0];
    const int*   tt   = (const int*)  d_in[1];
    const float* W_ih = (const float*)d_in[2];
    const float* W_hh = (const float*)d_in[3];
    const float* b_ih = (const float*)d_in[4];
    const float* b_hh = (const float*)d_in[5];
    const float* W1   = (const float*)d_in[6];
    const float* b1   = (const float*)d_in[7];
    const float* g1   = (const float*)d_in[8];
    const float* be1  = (const float*)d_in[9];
    const float* rm1  = (const float*)d_in[10];
    const float* rv1  = (const float*)d_in[11];
    const float* W2   = (const float*)d_in[12];
    const float* b2   = (const float*)d_in[13];
    const float* g2   = (const float*)d_in[14];
    const float* be2  = (const float*)d_in[15];
    const float* rm2  = (const float*)d_in[16];
    const float* rv2  = (const float*)d_in[17];
    const float* W3   = (const float*)d_in[18];
    const float* b3   = (const float*)d_in[19];
    const float* g3   = (const float*)d_in[20];
    const float* be3  = (const float*)d_in[21];
    const float* rm3  = (const float*)d_in[22];
    const float* rv3  = (const float*)d_in[23];
    float* out = (float*)d_out;

    float *prex, *hs, *z1, *z2, *y, *xall, *hA, *hB, *z1d, *z2d;
    float *xr, *wih, *whh, *w1, *w2, *w3;
    cudaGetSymbolAddress((void**)&prex, g_prex);
    cudaGetSymbolAddress((void**)&hs,   g_hs);
    cudaGetSymbolAddress((void**)&z1,   g_z1);
    cudaGetSymbolAddress((void**)&z2,   g_z2);
    cudaGetSymbolAddress((void**)&y,    g_y);
    cudaGetSymbolAddress((void**)&xall, g_xall);
    cudaGetSymbolAddress((void**)&hA,   g_hA);
    cudaGetSymbolAddress((void**)&hB,   g_hB);
    cudaGetSymbolAddress((void**)&z1d,  g_z1d);
    cudaGetSymbolAddress((void**)&z2d,  g_z2d);
    cudaGetSymbolAddress((void**)&xr,   g_xr);
    cudaGetSymbolAddress((void**)&wih,  g_wih);
    cudaGetSymbolAddress((void**)&whh,  g_whh);
    cudaGetSymbolAddress((void**)&w1,   g_w1);
    cudaGetSymbolAddress((void**)&w2,   g_w2);
    cudaGetSymbolAddress((void**)&w3,   g_w3);

    const int BIGM = TT * BSZ;

    cudaFuncSetAttribute(scan_k, cudaFuncAttributeMaxDynamicSharedMemorySize,
                         SC_SMEM);
    cudaFuncSetAttribute(pdec_k, cudaFuncAttributeMaxDynamicSharedMemorySize,
                         PD_SMEM);
    cudaFuncSetAttribute(tgemm_k<0, 0>,
                         cudaFuncAttributeMaxDynamicSharedMemorySize, TG_SMEM);
    cudaFuncSetAttribute(tgemm_k<2, 0>,
                         cudaFuncAttributeMaxDynamicSharedMemorySize, TG_SMEM);
    cudaFuncSetAttribute(tgemm_k<3, 0>,
                         cudaFuncAttributeMaxDynamicSharedMemorySize, TG_SMEM);

    // 0. zero accumulators + pre-round all GEMM inputs (one launch)
    round_all_k<<<2048, 256>>>(x, W_ih, W_hh, W1, W2, W3);

    // 1. prex = x @ W_ih^T + b_ih
    runtg<0>(xr, wih, FEAT, b_ih, nullptr, nullptr, nullptr, nullptr,
             prex, BIGM, FEAT, BSZ, FEAT, TTOT * FEAT);

    // 2. full RNN scan — persistent tensor-core kernel
    scan_k<<<SCAN_GRID, 256, SC_SMEM>>>(prex, whh, b_hh, hs);

    // 3. autoencoder; layer 3 fuses loss1
    runtg<2>(hs, w1, FEAT, b1, g1, rm1, rv1, be1, z1, BIGM, HID,
             NOROW, 0, FEAT);
    runtg<2>(z1, w2, HID, b2, g2, rm2, rv2, be2, z2, BIGM, HID,
             NOROW, 0, HID);
    runtg<3>(z2, w3, HID, b3, g3, rm3, rv3, be3, y, BIGM, FEAT,
             NOROW, 0, HID, x);

    // 4. decode — ONE persistent kernel, all 16 iterations
    pdec_k<<<PDEC_GRID, 256, PD_SMEM>>>(
        hs, y, wih, whh, b_ih, b_hh,
        w1, b1, g1, rm1, rv1, be1,
        w2, b2, g2, rm2, rv2, be2,
        w3, b3, g3, rm3, rv3, be3,
        hA, hB, z1d, z2d, xall);

    // 5. gather x_pred + loss2, finalize scalar loss
    gather_k<<<BSZ * FEAT / 256, 256>>>(xall, tt, x, out);
    if (out_size > BSZ * FEAT) fin_k<<<1, 1>>>(out);
}